// round 6
// baseline (speedup 1.0000x reference)
#include <cuda_runtime.h>
#include <cuda_fp16.h>
#include <cstdint>

#define NTOK 8192
#define DIM  2048
#define NEXP 8
#define TOPK 2

#define BM 128
#define BN 128
#define BK 64                          // halves per k-iter
#define STAGES 3
#define KITERS (DIM / BK)              // 32

#define MAXTILES 160
#define GRID_ROWTILES 136

#define STAGE_BYTES (BM * BK * 2)      // 16384
#define SMEM_TOTAL  (2 * STAGES * STAGE_BYTES)  // 98304

#define GATE_BLOCKS 1024               // 8 warps/block, 1 token/warp
#define CONV_BLOCKS 2048               // W-convert + out-zero slices
#define PREP_BLOCKS (GATE_BLOCKS + CONV_BLOCKS)

// ---------------- device globals ----------------
__device__ int    g_count[NEXP];
__device__ int    g_tok[NEXP * NTOK];
__device__ float  g_wt [NEXP * NTOK];
__device__ int    g_ntiles;
__device__ int    g_tile_e[MAXTILES];
__device__ int    g_tile_r[MAXTILES];
__device__ __half g_xh[(size_t)NEXP * NTOK * DIM];   // per-expert padded fp16 A
__device__ __half g_wh[(size_t)NEXP * DIM * DIM];    // fp16 W

// ---------------- helpers ----------------
__device__ __forceinline__ uint32_t smem_u32(const void* p) {
    uint32_t a;
    asm("{ .reg .u64 t; cvta.to.shared.u64 t, %1; cvt.u32.u64 %0, t; }" : "=r"(a) : "l"(p));
    return a;
}
#define CP16(dst, src) \
    asm volatile("cp.async.cg.shared.global [%0], [%1], 16;" :: "r"(dst), "l"(src) : "memory")
#define CP_COMMIT() asm volatile("cp.async.commit_group;" ::: "memory")
#define CP_WAIT1()  asm volatile("cp.async.wait_group 1;" ::: "memory")
#define CP_WAIT0()  asm volatile("cp.async.wait_group 0;" ::: "memory")

#define LDSM4(r0, r1, r2, r3, addr) \
    asm volatile("ldmatrix.sync.aligned.m8n8.x4.shared.b16 {%0,%1,%2,%3}, [%4];" \
        : "=r"(r0), "=r"(r1), "=r"(r2), "=r"(r3) : "r"(addr))

__device__ __forceinline__ void mma_f16(float* d, const uint32_t* a, const uint32_t* b) {
    asm volatile(
        "mma.sync.aligned.m16n8k16.row.col.f32.f16.f16.f32 "
        "{%0,%1,%2,%3}, {%4,%5,%6,%7}, {%8,%9}, {%0,%1,%2,%3};"
        : "+f"(d[0]), "+f"(d[1]), "+f"(d[2]), "+f"(d[3])
        : "r"(a[0]), "r"(a[1]), "r"(a[2]), "r"(a[3]), "r"(b[0]), "r"(b[1]));
}

// ---------------- kernel 0: init counters ----------------
__global__ void init_kernel() {
    if (threadIdx.x < NEXP) g_count[threadIdx.x] = 0;
}

// ---------------- kernel 1: fused prep ----------------
// blocks [0, GATE_BLOCKS): gating (1 warp/token) + fp16 row scatter into
//   per-expert padded slots.
// blocks [GATE_BLOCKS, PREP_BLOCKS): W fp32->fp16 slice + out-zero slice.
__global__ void __launch_bounds__(256)
prep_kernel(const float* __restrict__ x,
            const float4* __restrict__ W,
            const float* __restrict__ Wg,
            const float* __restrict__ bg,
            float4* __restrict__ out) {
    int bid = blockIdx.x;
    int tid = threadIdx.x;

    if (bid >= GATE_BLOCKS) {
        int cid = bid - GATE_BLOCKS;
        {
            __half2* dst = (__half2*)g_wh;
            size_t base = (size_t)cid * 4096 + tid;
#pragma unroll 4
            for (int i = 0; i < 16; i++) {
                size_t idx = base + (size_t)i * 256;
                float4 v = W[idx];
                dst[2 * idx]     = __floats2half2_rn(v.x, v.y);
                dst[2 * idx + 1] = __floats2half2_rn(v.z, v.w);
            }
        }
        {
            float4 z = make_float4(0.f, 0.f, 0.f, 0.f);
            size_t base = (size_t)cid * 2048 + tid;
#pragma unroll
            for (int i = 0; i < 8; i++)
                out[base + (size_t)i * 256] = z;
        }
        return;
    }

    int wid  = tid >> 5;
    int lane = tid & 31;
    int tok  = bid * 8 + wid;

    const float* xr = x + (size_t)tok * DIM;
    float acc[NEXP];
#pragma unroll
    for (int e = 0; e < NEXP; e++) acc[e] = 0.f;
    for (int i = lane; i < DIM; i += 32) {
        float xv = xr[i];
#pragma unroll
        for (int e = 0; e < NEXP; e++)
            acc[e] = fmaf(xv, Wg[e * DIM + i], acc[e]);
    }
#pragma unroll
    for (int off = 16; off; off >>= 1)
#pragma unroll
        for (int e = 0; e < NEXP; e++)
            acc[e] += __shfl_xor_sync(0xffffffffu, acc[e], off);

    int i0 = 0, i1 = 0, p0 = 0, p1 = 0;
    if (lane == 0) {
        float m = -3.4e38f;
#pragma unroll
        for (int e = 0; e < NEXP; e++) { acc[e] += bg[e]; m = fmaxf(m, acc[e]); }
        float p[NEXP], s = 0.f;
#pragma unroll
        for (int e = 0; e < NEXP; e++) { p[e] = expf(acc[e] - m); s += p[e]; }
        i0 = 0;
#pragma unroll
        for (int e = 1; e < NEXP; e++) if (p[e] > p[i0]) i0 = e;
        i1 = (i0 == 0) ? 1 : 0;
#pragma unroll
        for (int e = 0; e < NEXP; e++)
            if (e != i0 && p[e] > p[i1]) i1 = e;

        float inv = 1.f / s;
        p0 = atomicAdd(&g_count[i0], 1);
        p1 = atomicAdd(&g_count[i1], 1);
        g_tok[i0 * NTOK + p0] = tok;  g_wt[i0 * NTOK + p0] = p[i0] * inv;
        g_tok[i1 * NTOK + p1] = tok;  g_wt[i1 * NTOK + p1] = p[i1] * inv;
    }
    i0 = __shfl_sync(0xffffffffu, i0, 0);
    i1 = __shfl_sync(0xffffffffu, i1, 0);
    p0 = __shfl_sync(0xffffffffu, p0, 0);
    p1 = __shfl_sync(0xffffffffu, p1, 0);

    const float4* src = (const float4*)xr;
    __half2* d0 = (__half2*)(g_xh + ((size_t)i0 * NTOK + p0) * DIM);
    __half2* d1 = (__half2*)(g_xh + ((size_t)i1 * NTOK + p1) * DIM);
    for (int i = lane; i < DIM / 4; i += 32) {
        float4 v = src[i];
        __half2 h0 = __floats2half2_rn(v.x, v.y);
        __half2 h1 = __floats2half2_rn(v.z, v.w);
        d0[2 * i] = h0; d0[2 * i + 1] = h1;
        d1[2 * i] = h0; d1[2 * i + 1] = h1;
    }
}

// ---------------- kernel 2: schedule tiles ----------------
__global__ void sched_kernel() {
    if (threadIdx.x == 0) {
        int nt = 0;
        for (int e = 0; e < NEXP; e++) {
            int c = g_count[e];
            int t = (c + BM - 1) / BM;
            for (int i = 0; i < t; i++) { g_tile_e[nt] = e; g_tile_r[nt] = i * BM; nt++; }
        }
        g_ntiles = nt;
    }
}

// ---------------- kernel 3: FP16 mma.sync grouped GEMM ----------------
// 128 threads, warps 2(M)x2(N), warp tile 64x64 (32 HMMA / 8 LDSM.x4 per k16),
// 3-stage cp.async, ONE barrier per k-tile, atomic epilogue.
__global__ void __launch_bounds__(128, 2)
moe_mma_gemm(const float* __restrict__ bias, float* __restrict__ out) {
    int bx = blockIdx.x;
    if (bx >= g_ntiles) return;
    int e   = g_tile_e[bx];
    int r0  = g_tile_r[bx];
    int cnt = g_count[e];
    int n0  = blockIdx.y * BN;

    extern __shared__ char smem[];
    uint32_t sbase = smem_u32(smem);

    int tid    = threadIdx.x;
    int lane   = tid & 31;
    int wid    = tid >> 5;
    int warp_m = wid & 1;          // 64-row slab
    int warp_n = wid >> 1;         // 64-col slab
    int fr     = lane >> 2;
    int fc     = lane & 3;

    // global loads: 1 thread per row, 8x16B chunks
    const __half* gA = g_xh + ((size_t)e * NTOK + r0 + tid) * DIM;
    const __half* gB = g_wh + ((size_t)e * DIM + n0 + tid) * DIM;
    uint32_t rowOff = tid * 128;
    int      rSw    = tid & 7;

    // ldmatrix lane addressing
    int mi  = lane >> 3;
    int r8  = lane & 7;
    int aCh = mi >> 1;
    uint32_t aBase[4];
    int      aSw[4];
#pragma unroll
    for (int tm = 0; tm < 4; tm++) {
        int r = warp_m * 64 + tm * 16 + (mi & 1) * 8 + r8;
        aBase[tm] = r * 128;
        aSw[tm]   = r & 7;
    }
    int bCh = mi & 1;
    uint32_t bBase[4];
    int      bSw[4];
#pragma unroll
    for (int p = 0; p < 4; p++) {
        int r = warp_n * 64 + (2 * p + (mi >> 1)) * 8 + r8;
        bBase[p] = r * 128;
        bSw[p]   = r & 7;
    }

    float acc[4][8][4];
#pragma unroll
    for (int i = 0; i < 4; i++)
#pragma unroll
        for (int j = 0; j < 8; j++)
#pragma unroll
            for (int k = 0; k < 4; k++) acc[i][j][k] = 0.f;

    auto load_stage = [&](int s, int kt) {
        uint32_t da = sbase + s * STAGE_BYTES + rowOff;
        uint32_t db = sbase + (STAGES + s) * STAGE_BYTES + rowOff;
        const __half* pa = gA + kt * BK;
        const __half* pb = gB + kt * BK;
#pragma unroll
        for (int c = 0; c < 8; c++) {
            uint32_t pc = (uint32_t)(c ^ rSw) << 4;
            CP16(da + pc, pa + c * 8);
            CP16(db + pc, pb + c * 8);
        }
        CP_COMMIT();
    };

#pragma unroll
    for (int s = 0; s < STAGES - 1; s++) load_stage(s, s);

#pragma unroll 1
    for (int kt = 0; kt < KITERS; kt++) {
        if (kt < KITERS - 1) { CP_WAIT1(); } else { CP_WAIT0(); }
        __syncthreads();   // single barrier: prior iter's reads done, my stage ready

        int kp = kt + STAGES - 1;
        if (kp < KITERS) load_stage(kp % STAGES, kp);

        uint32_t As = sbase + (kt % STAGES) * STAGE_BYTES;
        uint32_t Bs = sbase + (STAGES + (kt % STAGES)) * STAGE_BYTES;

#pragma unroll
        for (int kk = 0; kk < BK / 16; kk++) {
            uint32_t a[4][4], bf[16];
#pragma unroll
            for (int tm = 0; tm < 4; tm++) {
                uint32_t addr = As + aBase[tm] +
                                ((uint32_t)((kk * 2 + aCh) ^ aSw[tm]) << 4);
                LDSM4(a[tm][0], a[tm][1], a[tm][2], a[tm][3], addr);
            }
#pragma unroll
            for (int p = 0; p < 4; p++) {
                uint32_t addr = Bs + bBase[p] +
                                ((uint32_t)((kk * 2 + bCh) ^ bSw[p]) << 4);
                LDSM4(bf[4 * p], bf[4 * p + 1], bf[4 * p + 2], bf[4 * p + 3], addr);
            }
#pragma unroll
            for (int tm = 0; tm < 4; tm++)
#pragma unroll
                for (int tn = 0; tn < 8; tn++)
                    mma_f16(acc[tm][tn], a[tm], &bf[tn * 2]);
        }
    }

    // epilogue: bias + relu + gate weight -> atomicAdd into out
    int c2 = 2 * fc;
    float2 bv[8];
#pragma unroll
    for (int tn = 0; tn < 8; tn++) {
        const float* bp = bias + (size_t)e * DIM + n0 + warp_n * 64 + tn * 8 + c2;
        bv[tn] = make_float2(__ldg(bp), __ldg(bp + 1));
    }
#pragma unroll
    for (int tm = 0; tm < 4; tm++) {
#pragma unroll
        for (int half = 0; half < 2; half++) {
            int row = warp_m * 64 + tm * 16 + half * 8 + fr;
            int idx = r0 + row;
            if (idx >= cnt) continue;
            int   tok = g_tok[e * NTOK + idx];
            float wgt = g_wt [e * NTOK + idx];
            float* orow = out + (size_t)tok * DIM + n0 + warp_n * 64;
#pragma unroll
            for (int tn = 0; tn < 8; tn++) {
                float v0 = fmaxf(acc[tm][tn][half * 2 + 0] + bv[tn].x, 0.f) * wgt;
                float v1 = fmaxf(acc[tm][tn][half * 2 + 1] + bv[tn].y, 0.f) * wgt;
                atomicAdd(orow + tn * 8 + c2,     v0);
                atomicAdd(orow + tn * 8 + c2 + 1, v1);
            }
        }
    }
}

// ---------------- launch ----------------
extern "C" void kernel_launch(void* const* d_in, const int* in_sizes, int n_in,
                              void* d_out, int out_size) {
    const float* x  = (const float*)d_in[0];
    const float* W  = (const float*)d_in[1];
    const float* b  = (const float*)d_in[2];
    const float* Wg = (const float*)d_in[3];
    const float* bg = (const float*)d_in[4];
    float* out = (float*)d_out;
    (void)in_sizes; (void)n_in; (void)out_size;

    cudaFuncSetAttribute(moe_mma_gemm, cudaFuncAttributeMaxDynamicSharedMemorySize, SMEM_TOTAL);

    init_kernel<<<1, 32>>>();
    prep_kernel<<<PREP_BLOCKS, 256>>>(x, (const float4*)W, Wg, bg, (float4*)out);
    sched_kernel<<<1, 32>>>();
    moe_mma_gemm<<<dim3(GRID_ROWTILES, DIM / BN), 128, SMEM_TOTAL>>>(b, out);
}

// round 8
// speedup vs baseline: 1.1501x; 1.1501x over previous
#include <cuda_runtime.h>
#include <cuda_fp16.h>
#include <cstdint>

#define NTOK 8192
#define DIM  2048
#define NEXP 8
#define TOPK 2

#define BM 128
#define BN 128
#define BK 64                          // halves per k-iter
#define STAGES 4
#define KITERS (DIM / BK)              // 32

#define MAXTILES 160
#define GRID_ROWTILES 136

#define STAGE_BYTES (BM * BK * 2)      // 16384
#define SMEM_TOTAL  (2 * STAGES * STAGE_BYTES)  // 131072

#define GATE_BLOCKS 1024               // 8 warps/block, 1 token/warp
#define CONV_BLOCKS 2048               // W-convert + out-zero slices
#define PREP_BLOCKS (GATE_BLOCKS + CONV_BLOCKS)

// ---------------- device globals ----------------
__device__ int    g_count[NEXP];
__device__ int    g_tok[NEXP * NTOK];
__device__ float  g_wt [NEXP * NTOK];
__device__ int    g_ntiles;
__device__ int    g_tile_e[MAXTILES];
__device__ int    g_tile_r[MAXTILES];
__device__ __half g_xh[(size_t)NEXP * NTOK * DIM];   // per-expert padded fp16 A
__device__ __half g_wh[(size_t)NEXP * DIM * DIM];    // fp16 W

// ---------------- helpers ----------------
__device__ __forceinline__ uint32_t smem_u32(const void* p) {
    uint32_t a;
    asm("{ .reg .u64 t; cvta.to.shared.u64 t, %1; cvt.u32.u64 %0, t; }" : "=r"(a) : "l"(p));
    return a;
}
#define CP16(dst, src) \
    asm volatile("cp.async.cg.shared.global [%0], [%1], 16;" :: "r"(dst), "l"(src) : "memory")
#define CP_COMMIT() asm volatile("cp.async.commit_group;" ::: "memory")
#define CP_WAIT2()  asm volatile("cp.async.wait_group 2;" ::: "memory")
#define CP_WAIT0()  asm volatile("cp.async.wait_group 0;" ::: "memory")

#define LDSM4(r0, r1, r2, r3, addr) \
    asm volatile("ldmatrix.sync.aligned.m8n8.x4.shared.b16 {%0,%1,%2,%3}, [%4];" \
        : "=r"(r0), "=r"(r1), "=r"(r2), "=r"(r3) : "r"(addr))

__device__ __forceinline__ void mma_f16(float* d, const uint32_t* a, const uint32_t* b) {
    asm volatile(
        "mma.sync.aligned.m16n8k16.row.col.f32.f16.f16.f32 "
        "{%0,%1,%2,%3}, {%4,%5,%6,%7}, {%8,%9}, {%0,%1,%2,%3};"
        : "+f"(d[0]), "+f"(d[1]), "+f"(d[2]), "+f"(d[3])
        : "r"(a[0]), "r"(a[1]), "r"(a[2]), "r"(a[3]), "r"(b[0]), "r"(b[1]));
}

// ---------------- kernel 0: init counters ----------------
__global__ void init_kernel() {
    if (threadIdx.x < NEXP) g_count[threadIdx.x] = 0;
}

// ---------------- kernel 1: fused prep ----------------
__global__ void __launch_bounds__(256)
prep_kernel(const float* __restrict__ x,
            const float4* __restrict__ W,
            const float* __restrict__ Wg,
            const float* __restrict__ bg,
            float4* __restrict__ out) {
    int bid = blockIdx.x;
    int tid = threadIdx.x;

    if (bid >= GATE_BLOCKS) {
        int cid = bid - GATE_BLOCKS;
        {
            __half2* dst = (__half2*)g_wh;
            size_t base = (size_t)cid * 4096 + tid;
#pragma unroll 4
            for (int i = 0; i < 16; i++) {
                size_t idx = base + (size_t)i * 256;
                float4 v = W[idx];
                dst[2 * idx]     = __floats2half2_rn(v.x, v.y);
                dst[2 * idx + 1] = __floats2half2_rn(v.z, v.w);
            }
        }
        {
            float4 z = make_float4(0.f, 0.f, 0.f, 0.f);
            size_t base = (size_t)cid * 2048 + tid;
#pragma unroll
            for (int i = 0; i < 8; i++)
                out[base + (size_t)i * 256] = z;
        }
        return;
    }

    int wid  = tid >> 5;
    int lane = tid & 31;
    int tok  = bid * 8 + wid;

    const float* xr = x + (size_t)tok * DIM;
    float acc[NEXP];
#pragma unroll
    for (int e = 0; e < NEXP; e++) acc[e] = 0.f;
    for (int i = lane; i < DIM; i += 32) {
        float xv = xr[i];
#pragma unroll
        for (int e = 0; e < NEXP; e++)
            acc[e] = fmaf(xv, Wg[e * DIM + i], acc[e]);
    }
#pragma unroll
    for (int off = 16; off; off >>= 1)
#pragma unroll
        for (int e = 0; e < NEXP; e++)
            acc[e] += __shfl_xor_sync(0xffffffffu, acc[e], off);

    int i0 = 0, i1 = 0, p0 = 0, p1 = 0;
    if (lane == 0) {
        float m = -3.4e38f;
#pragma unroll
        for (int e = 0; e < NEXP; e++) { acc[e] += bg[e]; m = fmaxf(m, acc[e]); }
        float p[NEXP], s = 0.f;
#pragma unroll
        for (int e = 0; e < NEXP; e++) { p[e] = expf(acc[e] - m); s += p[e]; }
        i0 = 0;
#pragma unroll
        for (int e = 1; e < NEXP; e++) if (p[e] > p[i0]) i0 = e;
        i1 = (i0 == 0) ? 1 : 0;
#pragma unroll
        for (int e = 0; e < NEXP; e++)
            if (e != i0 && p[e] > p[i1]) i1 = e;

        float inv = 1.f / s;
        p0 = atomicAdd(&g_count[i0], 1);
        p1 = atomicAdd(&g_count[i1], 1);
        g_tok[i0 * NTOK + p0] = tok;  g_wt[i0 * NTOK + p0] = p[i0] * inv;
        g_tok[i1 * NTOK + p1] = tok;  g_wt[i1 * NTOK + p1] = p[i1] * inv;
    }
    i0 = __shfl_sync(0xffffffffu, i0, 0);
    i1 = __shfl_sync(0xffffffffu, i1, 0);
    p0 = __shfl_sync(0xffffffffu, p0, 0);
    p1 = __shfl_sync(0xffffffffu, p1, 0);

    const float4* src = (const float4*)xr;
    __half2* d0 = (__half2*)(g_xh + ((size_t)i0 * NTOK + p0) * DIM);
    __half2* d1 = (__half2*)(g_xh + ((size_t)i1 * NTOK + p1) * DIM);
    for (int i = lane; i < DIM / 4; i += 32) {
        float4 v = src[i];
        __half2 h0 = __floats2half2_rn(v.x, v.y);
        __half2 h1 = __floats2half2_rn(v.z, v.w);
        d0[2 * i] = h0; d0[2 * i + 1] = h1;
        d1[2 * i] = h0; d1[2 * i + 1] = h1;
    }
}

// ---------------- kernel 2: schedule tiles ----------------
__global__ void sched_kernel() {
    if (threadIdx.x == 0) {
        int nt = 0;
        for (int e = 0; e < NEXP; e++) {
            int c = g_count[e];
            int t = (c + BM - 1) / BM;
            for (int i = 0; i < t; i++) { g_tile_e[nt] = e; g_tile_r[nt] = i * BM; nt++; }
        }
        g_ntiles = nt;
    }
}

// ---------------- kernel 3: FP16 mma.sync grouped GEMM ----------------
// 256 thr, warps 4(M)x2(N), warp tile 32x64, fragment DOUBLE-BUFFERED:
// LDSM for kk+1 overlaps HMMAs for kk (smem pipe || tensor pipe).
// 4-stage cp.async, one barrier per k-tile, atomic epilogue.
__global__ void __launch_bounds__(256, 1)
moe_mma_gemm(const float* __restrict__ bias, float* __restrict__ out) {
    int bx = blockIdx.x;
    if (bx >= g_ntiles) return;
    int e   = g_tile_e[bx];
    int r0  = g_tile_r[bx];
    int cnt = g_count[e];
    int n0  = blockIdx.y * BN;

    extern __shared__ char smem[];
    uint32_t sbase = smem_u32(smem);

    int tid    = threadIdx.x;
    int lane   = tid & 31;
    int wid    = tid >> 5;
    int warp_m = wid & 3;
    int warp_n = wid >> 2;
    int fr     = lane >> 2;
    int fc     = lane & 3;

    // global loads: 2 threads per row, 4x16B chunks each
    int lrow = tid >> 1;
    int cgrp = (tid & 1) * 4;
    const __half* gA = g_xh + ((size_t)e * NTOK + r0 + lrow) * DIM + cgrp * 8;
    const __half* gB = g_wh + ((size_t)e * DIM + n0 + lrow) * DIM + cgrp * 8;
    uint32_t rowOff = lrow * 128;
    int      rSw    = lrow & 7;

    int mi  = lane >> 3;
    int r8  = lane & 7;
    int aCh = mi >> 1;
    uint32_t aBase[2];
    int      aSw[2];
#pragma unroll
    for (int tm = 0; tm < 2; tm++) {
        int r = warp_m * 32 + tm * 16 + (mi & 1) * 8 + r8;
        aBase[tm] = r * 128;
        aSw[tm]   = r & 7;
    }
    int bCh = mi & 1;
    uint32_t bBase[4];
    int      bSw[4];
#pragma unroll
    for (int p = 0; p < 4; p++) {
        int r = warp_n * 64 + (2 * p + (mi >> 1)) * 8 + r8;
        bBase[p] = r * 128;
        bSw[p]   = r & 7;
    }

    float acc[2][8][4];
#pragma unroll
    for (int i = 0; i < 2; i++)
#pragma unroll
        for (int j = 0; j < 8; j++)
#pragma unroll
            for (int k = 0; k < 4; k++) acc[i][j][k] = 0.f;

    auto load_stage = [&](int s, int kt) {
        uint32_t da = sbase + s * STAGE_BYTES + rowOff;
        uint32_t db = sbase + (STAGES + s) * STAGE_BYTES + rowOff;
        const __half* pa = gA + kt * BK;
        const __half* pb = gB + kt * BK;
#pragma unroll
        for (int c = 0; c < 4; c++) {
            uint32_t pc = (uint32_t)((cgrp + c) ^ rSw) << 4;
            CP16(da + pc, pa + c * 8);
            CP16(db + pc, pb + c * 8);
        }
        CP_COMMIT();
    };

    // fragment double buffers
    uint32_t a[2][2][4], bf[2][16];

    auto load_frag = [&](int buf, int kk, uint32_t As, uint32_t Bs) {
#pragma unroll
        for (int tm = 0; tm < 2; tm++) {
            uint32_t addr = As + aBase[tm] +
                            ((uint32_t)((kk * 2 + aCh) ^ aSw[tm]) << 4);
            LDSM4(a[buf][tm][0], a[buf][tm][1], a[buf][tm][2], a[buf][tm][3], addr);
        }
#pragma unroll
        for (int p = 0; p < 4; p++) {
            uint32_t addr = Bs + bBase[p] +
                            ((uint32_t)((kk * 2 + bCh) ^ bSw[p]) << 4);
            LDSM4(bf[buf][4 * p], bf[buf][4 * p + 1],
                  bf[buf][4 * p + 2], bf[buf][4 * p + 3], addr);
        }
    };

#pragma unroll
    for (int s = 0; s < STAGES - 1; s++) load_stage(s, s);

#pragma unroll 1
    for (int kt = 0; kt < KITERS; kt++) {
        if (kt < KITERS - 1) { CP_WAIT2(); } else { CP_WAIT0(); }
        __syncthreads();   // all warps finished kt-1 reads; stage kt complete

        int kp = kt + STAGES - 1;
        if (kp < KITERS) load_stage(kp % STAGES, kp);

        uint32_t As = sbase + (kt % STAGES) * STAGE_BYTES;
        uint32_t Bs = sbase + (STAGES + (kt % STAGES)) * STAGE_BYTES;

        load_frag(0, 0, As, Bs);
#pragma unroll
        for (int kk = 0; kk < BK / 16; kk++) {
            int cur = kk & 1;
            if (kk < BK / 16 - 1) load_frag(cur ^ 1, kk + 1, As, Bs);
#pragma unroll
            for (int tm = 0; tm < 2; tm++)
#pragma unroll
                for (int tn = 0; tn < 8; tn++)
                    mma_f16(acc[tm][tn], a[cur][tm], &bf[cur][tn * 2]);
        }
    }

    // epilogue: bias + relu + gate weight -> atomicAdd into out
    int c2 = 2 * fc;
    float2 bv[8];
#pragma unroll
    for (int tn = 0; tn < 8; tn++) {
        const float* bp = bias + (size_t)e * DIM + n0 + warp_n * 64 + tn * 8 + c2;
        bv[tn] = make_float2(__ldg(bp), __ldg(bp + 1));
    }
#pragma unroll
    for (int tm = 0; tm < 2; tm++) {
#pragma unroll
        for (int half = 0; half < 2; half++) {
            int row = warp_m * 32 + tm * 16 + half * 8 + fr;
            int idx = r0 + row;
            if (idx >= cnt) continue;
            int   tok = g_tok[e * NTOK + idx];
            float wgt = g_wt [e * NTOK + idx];
            float* orow = out + (size_t)tok * DIM + n0 + warp_n * 64;
#pragma unroll
            for (int tn = 0; tn < 8; tn++) {
                float v0 = fmaxf(acc[tm][tn][half * 2 + 0] + bv[tn].x, 0.f) * wgt;
                float v1 = fmaxf(acc[tm][tn][half * 2 + 1] + bv[tn].y, 0.f) * wgt;
                atomicAdd(orow + tn * 8 + c2,     v0);
                atomicAdd(orow + tn * 8 + c2 + 1, v1);
            }
        }
    }
}

// ---------------- launch ----------------
extern "C" void kernel_launch(void* const* d_in, const int* in_sizes, int n_in,
                              void* d_out, int out_size) {
    const float* x  = (const float*)d_in[0];
    const float* W  = (const float*)d_in[1];
    const float* b  = (const float*)d_in[2];
    const float* Wg = (const float*)d_in[3];
    const float* bg = (const float*)d_in[4];
    float* out = (float*)d_out;
    (void)in_sizes; (void)n_in; (void)out_size;

    cudaFuncSetAttribute(moe_mma_gemm, cudaFuncAttributeMaxDynamicSharedMemorySize, SMEM_TOTAL);

    init_kernel<<<1, 32>>>();
    prep_kernel<<<PREP_BLOCKS, 256>>>(x, (const float4*)W, Wg, bg, (float4*)out);
    sched_kernel<<<1, 32>>>();
    moe_mma_gemm<<<dim3(GRID_ROWTILES, DIM / BN), 256, SMEM_TOTAL>>>(b, out);
}

// round 9
// speedup vs baseline: 1.4302x; 1.2435x over previous
#include <cuda_runtime.h>
#include <cuda_fp16.h>
#include <cstdint>

#define NTOK 8192
#define DIM  2048
#define NEXP 8
#define TOPK 2

#define BM 128
#define BN 128
#define BK 64                          // halves per k-iter
#define STAGES 3
#define KITERS (DIM / BK)              // 32

#define GRID_ROWTILES 136

#define STAGE_BYTES (BM * BK * 2)      // 16384
#define SMEM_TOTAL  (2 * STAGES * STAGE_BYTES)  // 98304

#define GATE_BLOCKS 1024               // 8 warps/block, 1 token/warp
#define CONV_BLOCKS 2048               // W-convert + out-zero slices
#define PREP_BLOCKS (GATE_BLOCKS + CONV_BLOCKS)

// ---------------- device globals ----------------
__device__ int    g_count[NEXP];
__device__ int    g_tok[NEXP * NTOK];
__device__ float  g_wt [NEXP * NTOK];
__device__ __half g_xh[(size_t)NEXP * NTOK * DIM];   // per-expert padded fp16 A
__device__ __half g_wh[(size_t)NEXP * DIM * DIM];    // fp16 W

// ---------------- helpers ----------------
__device__ __forceinline__ uint32_t smem_u32(const void* p) {
    uint32_t a;
    asm("{ .reg .u64 t; cvta.to.shared.u64 t, %1; cvt.u32.u64 %0, t; }" : "=r"(a) : "l"(p));
    return a;
}
#define CP16(dst, src) \
    asm volatile("cp.async.cg.shared.global [%0], [%1], 16;" :: "r"(dst), "l"(src) : "memory")
#define CP_COMMIT() asm volatile("cp.async.commit_group;" ::: "memory")
#define CP_WAIT1()  asm volatile("cp.async.wait_group 1;" ::: "memory")
#define CP_WAIT0()  asm volatile("cp.async.wait_group 0;" ::: "memory")

#define LDSM4(r0, r1, r2, r3, addr) \
    asm volatile("ldmatrix.sync.aligned.m8n8.x4.shared.b16 {%0,%1,%2,%3}, [%4];" \
        : "=r"(r0), "=r"(r1), "=r"(r2), "=r"(r3) : "r"(addr))

__device__ __forceinline__ void mma_f16(float* d, const uint32_t* a, const uint32_t* b) {
    asm volatile(
        "mma.sync.aligned.m16n8k16.row.col.f32.f16.f16.f32 "
        "{%0,%1,%2,%3}, {%4,%5,%6,%7}, {%8,%9}, {%0,%1,%2,%3};"
        : "+f"(d[0]), "+f"(d[1]), "+f"(d[2]), "+f"(d[3])
        : "r"(a[0]), "r"(a[1]), "r"(a[2]), "r"(a[3]), "r"(b[0]), "r"(b[1]));
}

// ---------------- kernel 0: init counters ----------------
__global__ void init_kernel() {
    if (threadIdx.x < NEXP) g_count[threadIdx.x] = 0;
}

// ---------------- kernel 1: fused prep ----------------
__global__ void __launch_bounds__(256)
prep_kernel(const float* __restrict__ x,
            const float4* __restrict__ W,
            const float* __restrict__ Wg,
            const float* __restrict__ bg,
            float4* __restrict__ out) {
    int bid = blockIdx.x;
    int tid = threadIdx.x;

    if (bid >= GATE_BLOCKS) {
        int cid = bid - GATE_BLOCKS;
        {
            __half2* dst = (__half2*)g_wh;
            size_t base = (size_t)cid * 4096 + tid;
#pragma unroll 4
            for (int i = 0; i < 16; i++) {
                size_t idx = base + (size_t)i * 256;
                float4 v = W[idx];
                dst[2 * idx]     = __floats2half2_rn(v.x, v.y);
                dst[2 * idx + 1] = __floats2half2_rn(v.z, v.w);
            }
        }
        {
            float4 z = make_float4(0.f, 0.f, 0.f, 0.f);
            size_t base = (size_t)cid * 2048 + tid;
#pragma unroll
            for (int i = 0; i < 8; i++)
                out[base + (size_t)i * 256] = z;
        }
        return;
    }

    int wid  = tid >> 5;
    int lane = tid & 31;
    int tok  = bid * 8 + wid;

    const float* xr = x + (size_t)tok * DIM;
    float acc[NEXP];
#pragma unroll
    for (int e = 0; e < NEXP; e++) acc[e] = 0.f;
    for (int i = lane; i < DIM; i += 32) {
        float xv = xr[i];
#pragma unroll
        for (int e = 0; e < NEXP; e++)
            acc[e] = fmaf(xv, Wg[e * DIM + i], acc[e]);
    }
#pragma unroll
    for (int off = 16; off; off >>= 1)
#pragma unroll
        for (int e = 0; e < NEXP; e++)
            acc[e] += __shfl_xor_sync(0xffffffffu, acc[e], off);

    int i0 = 0, i1 = 0, p0 = 0, p1 = 0;
    if (lane == 0) {
        float m = -3.4e38f;
#pragma unroll
        for (int e = 0; e < NEXP; e++) { acc[e] += bg[e]; m = fmaxf(m, acc[e]); }
        float p[NEXP], s = 0.f;
#pragma unroll
        for (int e = 0; e < NEXP; e++) { p[e] = expf(acc[e] - m); s += p[e]; }
        i0 = 0;
#pragma unroll
        for (int e = 1; e < NEXP; e++) if (p[e] > p[i0]) i0 = e;
        i1 = (i0 == 0) ? 1 : 0;
#pragma unroll
        for (int e = 0; e < NEXP; e++)
            if (e != i0 && p[e] > p[i1]) i1 = e;

        float inv = 1.f / s;
        p0 = atomicAdd(&g_count[i0], 1);
        p1 = atomicAdd(&g_count[i1], 1);
        g_tok[i0 * NTOK + p0] = tok;  g_wt[i0 * NTOK + p0] = p[i0] * inv;
        g_tok[i1 * NTOK + p1] = tok;  g_wt[i1 * NTOK + p1] = p[i1] * inv;
    }
    i0 = __shfl_sync(0xffffffffu, i0, 0);
    i1 = __shfl_sync(0xffffffffu, i1, 0);
    p0 = __shfl_sync(0xffffffffu, p0, 0);
    p1 = __shfl_sync(0xffffffffu, p1, 0);

    const float4* src = (const float4*)xr;
    __half2* d0 = (__half2*)(g_xh + ((size_t)i0 * NTOK + p0) * DIM);
    __half2* d1 = (__half2*)(g_xh + ((size_t)i1 * NTOK + p1) * DIM);
    for (int i = lane; i < DIM / 4; i += 32) {
        float4 v = src[i];
        __half2 h0 = __floats2half2_rn(v.x, v.y);
        __half2 h1 = __floats2half2_rn(v.z, v.w);
        d0[2 * i] = h0; d0[2 * i + 1] = h1;
        d1[2 * i] = h0; d1[2 * i + 1] = h1;
    }
}

// ---------------- kernel 2: FP16 mma.sync grouped GEMM ----------------
// 256 thr, warps 4(M)x2(N), warp tile 32x64.  In-warp pipelining:
// A frags double-buffered across k16 steps; B pairs loaded just-in-time
// (2-slot rotation) so LDSMs spread uniformly between HMMA groups.
// 3-stage cp.async, one barrier per k-tile, atomic epilogue, 2 CTAs/SM.
__global__ void __launch_bounds__(256, 2)
moe_mma_gemm(const float* __restrict__ bias, float* __restrict__ out) {
    int bx = blockIdx.x;

    // derive (expert, row-tile) from counts (sched kernel folded in here)
    int e = -1, r0 = 0, nt = 0;
#pragma unroll
    for (int i = 0; i < NEXP; i++) {
        int t = (g_count[i] + BM - 1) / BM;
        if (e < 0 && bx < nt + t) { e = i; r0 = (bx - nt) * BM; }
        nt += t;
    }
    if (e < 0) return;
    int cnt = g_count[e];
    int n0  = blockIdx.y * BN;

    extern __shared__ char smem[];
    uint32_t sbase = smem_u32(smem);

    int tid    = threadIdx.x;
    int lane   = tid & 31;
    int wid    = tid >> 5;
    int warp_m = wid & 3;
    int warp_n = wid >> 2;
    int fr     = lane >> 2;
    int fc     = lane & 3;

    // global loads: 2 threads per row, 4x16B chunks each
    int lrow = tid >> 1;
    int cgrp = (tid & 1) * 4;
    const __half* gA = g_xh + ((size_t)e * NTOK + r0 + lrow) * DIM + cgrp * 8;
    const __half* gB = g_wh + ((size_t)e * DIM + n0 + lrow) * DIM + cgrp * 8;
    uint32_t rowOff = lrow * 128;
    int      rSw    = lrow & 7;

    int mi  = lane >> 3;
    int r8  = lane & 7;
    int aCh = mi >> 1;
    uint32_t aBase[2];
    int      aSw[2];
#pragma unroll
    for (int tm = 0; tm < 2; tm++) {
        int r = warp_m * 32 + tm * 16 + (mi & 1) * 8 + r8;
        aBase[tm] = r * 128;
        aSw[tm]   = r & 7;
    }
    int bCh = mi & 1;
    uint32_t bBase[4];
    int      bSw[4];
#pragma unroll
    for (int p = 0; p < 4; p++) {
        int r = warp_n * 64 + (2 * p + (mi >> 1)) * 8 + r8;
        bBase[p] = r * 128;
        bSw[p]   = r & 7;
    }

    float acc[2][8][4];
#pragma unroll
    for (int i = 0; i < 2; i++)
#pragma unroll
        for (int j = 0; j < 8; j++)
#pragma unroll
            for (int k = 0; k < 4; k++) acc[i][j][k] = 0.f;

    auto load_stage = [&](int s, int kt) {
        uint32_t da = sbase + s * STAGE_BYTES + rowOff;
        uint32_t db = sbase + (STAGES + s) * STAGE_BYTES + rowOff;
        const __half* pa = gA + kt * BK;
        const __half* pb = gB + kt * BK;
#pragma unroll
        for (int c = 0; c < 4; c++) {
            uint32_t pc = (uint32_t)((cgrp + c) ^ rSw) << 4;
            CP16(da + pc, pa + c * 8);
            CP16(db + pc, pb + c * 8);
        }
        CP_COMMIT();
    };

    // fragment buffers: A double (per k16 step), B 2-slot pair rotation
    uint32_t a[2][2][4], b[2][4];

#pragma unroll
    for (int s = 0; s < STAGES - 1; s++) load_stage(s, s);

#pragma unroll 1
    for (int kt = 0; kt < KITERS; kt++) {
        if (kt < KITERS - 1) { CP_WAIT1(); } else { CP_WAIT0(); }
        __syncthreads();   // prior-iter reads done; stage kt resident

        uint32_t As = sbase + (kt % STAGES) * STAGE_BYTES;
        uint32_t Bs = sbase + (STAGES + (kt % STAGES)) * STAGE_BYTES;

        // first fragments of this k-tile (kk=0): A both tm + B pair 0
#pragma unroll
        for (int tm = 0; tm < 2; tm++) {
            uint32_t addr = As + aBase[tm] + ((uint32_t)(aCh ^ aSw[tm]) << 4);
            LDSM4(a[0][tm][0], a[0][tm][1], a[0][tm][2], a[0][tm][3], addr);
        }
        {
            uint32_t addr = Bs + bBase[0] + ((uint32_t)(bCh ^ bSw[0]) << 4);
            LDSM4(b[0][0], b[0][1], b[0][2], b[0][3], addr);
        }

        int kp = kt + STAGES - 1;
        if (kp < KITERS) load_stage(kp % STAGES, kp);

#pragma unroll
        for (int kk = 0; kk < BK / 16; kk++) {
            int cur = kk & 1;
            if (kk < BK / 16 - 1) {
#pragma unroll
                for (int tm = 0; tm < 2; tm++) {
                    uint32_t addr = As + aBase[tm] +
                                    ((uint32_t)(((kk + 1) * 2 + aCh) ^ aSw[tm]) << 4);
                    LDSM4(a[cur ^ 1][tm][0], a[cur ^ 1][tm][1],
                          a[cur ^ 1][tm][2], a[cur ^ 1][tm][3], addr);
                }
            }
#pragma unroll
            for (int p = 0; p < 4; p++) {
                int pb = p & 1;
                // JIT prefetch: next B pair (or pair 0 of next kk)
                if (p < 3) {
                    uint32_t addr = Bs + bBase[p + 1] +
                                    ((uint32_t)((kk * 2 + bCh) ^ bSw[p + 1]) << 4);
                    LDSM4(b[pb ^ 1][0], b[pb ^ 1][1], b[pb ^ 1][2], b[pb ^ 1][3], addr);
                } else if (kk < BK / 16 - 1) {
                    uint32_t addr = Bs + bBase[0] +
                                    ((uint32_t)(((kk + 1) * 2 + bCh) ^ bSw[0]) << 4);
                    LDSM4(b[pb ^ 1][0], b[pb ^ 1][1], b[pb ^ 1][2], b[pb ^ 1][3], addr);
                }
#pragma unroll
                for (int tm = 0; tm < 2; tm++) {
                    mma_f16(acc[tm][2 * p],     a[cur][tm], &b[pb][0]);
                    mma_f16(acc[tm][2 * p + 1], a[cur][tm], &b[pb][2]);
                }
            }
        }
    }

    // epilogue: bias + relu + gate weight -> atomicAdd into out
    int c2 = 2 * fc;
    float2 bv[8];
#pragma unroll
    for (int tn = 0; tn < 8; tn++) {
        const float* bp = bias + (size_t)e * DIM + n0 + warp_n * 64 + tn * 8 + c2;
        bv[tn] = make_float2(__ldg(bp), __ldg(bp + 1));
    }
#pragma unroll
    for (int tm = 0; tm < 2; tm++) {
#pragma unroll
        for (int half = 0; half < 2; half++) {
            int row = warp_m * 32 + tm * 16 + half * 8 + fr;
            int idx = r0 + row;
            if (idx >= cnt) continue;
            int   tok = g_tok[e * NTOK + idx];
            float wgt = g_wt [e * NTOK + idx];
            float* orow = out + (size_t)tok * DIM + n0 + warp_n * 64;
#pragma unroll
            for (int tn = 0; tn < 8; tn++) {
                float v0 = fmaxf(acc[tm][tn][half * 2 + 0] + bv[tn].x, 0.f) * wgt;
                float v1 = fmaxf(acc[tm][tn][half * 2 + 1] + bv[tn].y, 0.f) * wgt;
                atomicAdd(orow + tn * 8 + c2,     v0);
                atomicAdd(orow + tn * 8 + c2 + 1, v1);
            }
        }
    }
}

// ---------------- launch ----------------
extern "C" void kernel_launch(void* const* d_in, const int* in_sizes, int n_in,
                              void* d_out, int out_size) {
    const float* x  = (const float*)d_in[0];
    const float* W  = (const float*)d_in[1];
    const float* b  = (const float*)d_in[2];
    const float* Wg = (const float*)d_in[3];
    const float* bg = (const float*)d_in[4];
    float* out = (float*)d_out;
    (void)in_sizes; (void)n_in; (void)out_size;

    cudaFuncSetAttribute(moe_mma_gemm, cudaFuncAttributeMaxDynamicSharedMemorySize, SMEM_TOTAL);

    init_kernel<<<1, 32>>>();
    prep_kernel<<<PREP_BLOCKS, 256>>>(x, (const float4*)W, Wg, bg, (float4*)out);
    moe_mma_gemm<<<dim3(GRID_ROWTILES, DIM / BN), 256, SMEM_TOTAL>>>(b, out);
}